// round 6
// baseline (speedup 1.0000x reference)
#include <cuda_runtime.h>
#include <cuda_bf16.h>
#include <cstdint>

#define N_NODES 50000
#define MAX_E   800000
#define D_IN    128
#define D_HID   256
#define D_OUT   128

// ---------------- scratch (static device globals; no allocation) ----------------
__device__ float g_neigh1[(size_t)N_NODES * D_IN];
__device__ float g_h1[(size_t)N_NODES * D_HID];
__device__ float g_s2[(size_t)N_NODES * D_OUT];
__device__ float g_t2[(size_t)N_NODES * D_OUT];
__device__ float g_sA[N_NODES];
__device__ float g_sB[N_NODES];
__device__ int   g_cnt[N_NODES];
__device__ int   g_rowptr[N_NODES + 1];
__device__ int   g_cursor[N_NODES];
__device__ int   g_csr_src[MAX_E];

// pre-split bf16 weights, same (K,N) layout as the fp32 originals
__device__ __nv_bfloat16 g_w1s_h[D_IN * D_HID], g_w1s_l[D_IN * D_HID];
__device__ __nv_bfloat16 g_w1n_h[D_IN * D_HID], g_w1n_l[D_IN * D_HID];
__device__ __nv_bfloat16 g_w2s_h[D_HID * D_OUT], g_w2s_l[D_HID * D_OUT];
__device__ __nv_bfloat16 g_w2n_h[D_HID * D_OUT], g_w2n_l[D_HID * D_OUT];

// ---------------- helpers ----------------
__device__ __forceinline__ uint32_t smem_u32(const void* p) {
    uint32_t a;
    asm("{ .reg .u64 t; cvta.to.shared.u64 t, %1; cvt.u32.u64 %0, t; }" : "=r"(a) : "l"(p));
    return a;
}
__device__ __forceinline__ uint32_t bpack(__nv_bfloat16 a, __nv_bfloat16 b) {
    return (uint32_t)__bfloat16_as_ushort(a) | ((uint32_t)__bfloat16_as_ushort(b) << 16);
}
__device__ __forceinline__ void split4(float4 v, uint32_t* h, uint32_t* l) {
    __nv_bfloat16 hx = __float2bfloat16_rn(v.x);
    __nv_bfloat16 hy = __float2bfloat16_rn(v.y);
    __nv_bfloat16 hz = __float2bfloat16_rn(v.z);
    __nv_bfloat16 hw = __float2bfloat16_rn(v.w);
    h[0] = bpack(hx, hy);
    h[1] = bpack(hz, hw);
    __nv_bfloat16 lx = __float2bfloat16_rn(v.x - __bfloat162float(hx));
    __nv_bfloat16 ly = __float2bfloat16_rn(v.y - __bfloat162float(hy));
    __nv_bfloat16 lz = __float2bfloat16_rn(v.z - __bfloat162float(hz));
    __nv_bfloat16 lw = __float2bfloat16_rn(v.w - __bfloat162float(hw));
    l[0] = bpack(lx, ly);
    l[1] = bpack(lz, lw);
}

#define LDSM_X4(r0, r1, r2, r3, addr) \
    asm volatile("ldmatrix.sync.aligned.m8n8.x4.shared.b16 {%0,%1,%2,%3}, [%4];" \
                 : "=r"(r0), "=r"(r1), "=r"(r2), "=r"(r3) : "r"(addr))
#define LDSM_X4T(r0, r1, r2, r3, addr) \
    asm volatile("ldmatrix.sync.aligned.m8n8.x4.trans.shared.b16 {%0,%1,%2,%3}, [%4];" \
                 : "=r"(r0), "=r"(r1), "=r"(r2), "=r"(r3) : "r"(addr))
#define MMA_BF16(c, a, b) \
    asm volatile("mma.sync.aligned.m16n8k16.row.col.f32.bf16.bf16.f32 " \
                 "{%0,%1,%2,%3}, {%4,%5,%6,%7}, {%8,%9}, {%0,%1,%2,%3};" \
                 : "+f"((c)[0]), "+f"((c)[1]), "+f"((c)[2]), "+f"((c)[3]) \
                 : "r"((a)[0]), "r"((a)[1]), "r"((a)[2]), "r"((a)[3]), \
                   "r"((b)[0]), "r"((b)[1]))
#define CP_ASYNC16(saddr, gptr) \
    asm volatile("cp.async.cg.shared.global [%0], [%1], 16;" :: "r"(saddr), "l"(gptr))
#define CP_COMMIT() asm volatile("cp.async.commit_group;")
#define CP_WAIT(n)  asm volatile("cp.async.wait_group %0;" :: "n"(n))

// ---------------- CSR build ----------------
__global__ void k_zero_cnt() {
    int i = blockIdx.x * blockDim.x + threadIdx.x;
    if (i < N_NODES) g_cnt[i] = 0;
}
__global__ void k_hist(const int* __restrict__ dst, int E) {
    int e = blockIdx.x * blockDim.x + threadIdx.x;
    if (e < E) atomicAdd(&g_cnt[dst[e]], 1);
}
__global__ void k_scan() {
    const int T = 1024;
    const int C = (N_NODES + T - 1) / T;
    __shared__ int partial[T];
    int t = threadIdx.x;
    int base = t * C;
    int s = 0;
    for (int i = 0; i < C; i++) {
        int idx = base + i;
        if (idx < N_NODES) s += g_cnt[idx];
    }
    partial[t] = s;
    __syncthreads();
    for (int off = 1; off < T; off <<= 1) {
        int v = (t >= off) ? partial[t - off] : 0;
        __syncthreads();
        partial[t] += v;
        __syncthreads();
    }
    int run = partial[t] - s;
    for (int i = 0; i < C; i++) {
        int idx = base + i;
        if (idx < N_NODES) {
            g_rowptr[idx] = run;
            g_cursor[idx] = run;
            run += g_cnt[idx];
        }
    }
    if (t == 0) g_rowptr[N_NODES] = partial[T - 1];
}
__global__ void k_fill(const int* __restrict__ src, const int* __restrict__ dst, int E) {
    int e = blockIdx.x * blockDim.x + threadIdx.x;
    if (e < E) {
        int d = dst[e];
        int pos = atomicAdd(&g_cursor[d], 1);
        g_csr_src[pos] = src[e];
    }
}

// ---------------- layer-1 aggregation (unrolled x2) ----------------
__global__ void k_agg128(const float* __restrict__ feat, float* __restrict__ out) {
    int warps_per_blk = blockDim.x >> 5;
    int n = blockIdx.x * warps_per_blk + (threadIdx.x >> 5);
    if (n >= N_NODES) return;
    int lane = threadIdx.x & 31;
    int beg = g_rowptr[n], end = g_rowptr[n + 1];

    float4 acc0 = {0.f, 0.f, 0.f, 0.f};
    float4 acc1 = {0.f, 0.f, 0.f, 0.f};
    int j = beg;
    for (; j + 1 < end; j += 2) {
        int s0 = g_csr_src[j];
        int s1 = g_csr_src[j + 1];
        float4 v0 = __ldg(&((const float4*)(feat + (size_t)s0 * 128))[lane]);
        float4 v1 = __ldg(&((const float4*)(feat + (size_t)s1 * 128))[lane]);
        acc0.x += v0.x; acc0.y += v0.y; acc0.z += v0.z; acc0.w += v0.w;
        acc1.x += v1.x; acc1.y += v1.y; acc1.z += v1.z; acc1.w += v1.w;
    }
    if (j < end) {
        int s0 = g_csr_src[j];
        float4 v0 = __ldg(&((const float4*)(feat + (size_t)s0 * 128))[lane]);
        acc0.x += v0.x; acc0.y += v0.y; acc0.z += v0.z; acc0.w += v0.w;
    }
    acc0.x += acc1.x; acc0.y += acc1.y; acc0.z += acc1.z; acc0.w += acc1.w;
    int deg = end - beg;
    float inv = (deg > 0) ? 1.f / (float)deg : 0.f;
    float4 o = {acc0.x * inv, acc0.y * inv, acc0.z * inv, acc0.w * inv};
    ((float4*)(out + (size_t)n * 128))[lane] = o;
}

// ---------------- weight split: all 4 matrices, one launch ----------------
// each matrix is exactly 32768 elements (128*256 or 256*128)
__global__ void k_wprep_all(
    const float* __restrict__ W1s, const float* __restrict__ W1n,
    const float* __restrict__ W2s, const float* __restrict__ W2n)
{
    int i = blockIdx.x * blockDim.x + threadIdx.x;
    if (i >= 4 * 32768) return;
    int a = i >> 15, r = i & 32767;
    const float* W = (a == 0) ? W1s : (a == 1) ? W1n : (a == 2) ? W2s : W2n;
    __nv_bfloat16* hi = (a == 0) ? g_w1s_h : (a == 1) ? g_w1n_h : (a == 2) ? g_w2s_h : g_w2n_h;
    __nv_bfloat16* lo = (a == 0) ? g_w1s_l : (a == 1) ? g_w1n_l : (a == 2) ? g_w2s_l : g_w2n_l;
    float w = W[r];
    __nv_bfloat16 h = __float2bfloat16_rn(w);
    hi[r] = h;
    lo[r] = __float2bfloat16_rn(w - __bfloat162float(h));
}

// ================= bf16x3 mma.sync GEMMs (pipelined) =================
// CTA tile 128(M) x 64(N), BK=32. 8 warps: wm=wid&3 (M), wn=wid>>2 (N).
// A tiles: 128 rows x 40 bf16 (80B row), single-buffered, register-prefetched.
// B tiles: 32 rows x 72 bf16 (144B row), double-buffered via cp.async.
#define A_TILE_B 10240
#define B_TILE_B 4608

// -------- layer 1: C = relu(A1@B1 + A2@B2 + bias) --------
__global__ void __launch_bounds__(256) k_mm_dual(
    const float* __restrict__ A1, const float* __restrict__ A2,
    const __nv_bfloat16* __restrict__ B1h, const __nv_bfloat16* __restrict__ B1l,
    const __nv_bfloat16* __restrict__ B2h, const __nv_bfloat16* __restrict__ B2l,
    const float* __restrict__ bias, float* __restrict__ C,
    int M, int N, int K)
{
    extern __shared__ char smem[];
    const int OA1H = 0, OA1L = A_TILE_B, OA2H = 2 * A_TILE_B, OA2L = 3 * A_TILE_B;
    const int OB_BASE = 4 * A_TILE_B;
    uint32_t sb = smem_u32(smem);

    int tid = threadIdx.x, lane = tid & 31, wid = tid >> 5;
    int wm = wid & 3, wn = wid >> 2;
    int bm = blockIdx.y * 128, bn = blockIdx.x * 64;
    const int nch = K >> 5;

    // B cp.async slot for this thread
    int brow = tid >> 3, bseg = tid & 7;
    uint32_t bso = (uint32_t)(brow * 144 + bseg * 16);
    const __nv_bfloat16* gB[4] = {B1h, B1l, B2h, B2l};

    // A slots
    int arow[4], ak4[4];
#pragma unroll
    for (int q = 0; q < 4; q++) {
        int slot = tid + q * 256;
        arow[q] = slot >> 3;
        ak4[q] = (slot & 7) * 4;
    }

    float acc[2][4][4];
#pragma unroll
    for (int i = 0; i < 2; i++)
#pragma unroll
        for (int j = 0; j < 4; j++)
#pragma unroll
            for (int q = 0; q < 4; q++) acc[i][j][q] = 0.f;

    float4 pv1[4], pv2[4];

    // prologue: B(chunk0) async, A(chunk0) into regs
    {
        size_t ge = (size_t)brow * N + bn + bseg * 8;
#pragma unroll
        for (int t = 0; t < 4; t++)
            CP_ASYNC16(sb + OB_BASE + t * B_TILE_B + bso, gB[t] + ge);
        CP_COMMIT();
#pragma unroll
        for (int q = 0; q < 4; q++) {
            int gr = bm + arow[q];
            pv1[q] = make_float4(0.f, 0.f, 0.f, 0.f);
            pv2[q] = make_float4(0.f, 0.f, 0.f, 0.f);
            if (gr < M) {
                pv1[q] = *(const float4*)(A1 + (size_t)gr * K + ak4[q]);
                pv2[q] = *(const float4*)(A2 + (size_t)gr * K + ak4[q]);
            }
        }
    }

    for (int chunk = 0; chunk < nch; chunk++) {
        int buf = chunk & 1;
        int obuf = OB_BASE + buf * 4 * B_TILE_B;

        // store prefetched A regs into smem (split hi/lo)
#pragma unroll
        for (int q = 0; q < 4; q++) {
            uint32_t h[2], l[2];
            int si = arow[q] * 20 + (ak4[q] >> 1);
            split4(pv1[q], h, l);
            ((uint32_t*)(smem + OA1H))[si] = h[0];
            ((uint32_t*)(smem + OA1H))[si + 1] = h[1];
            ((uint32_t*)(smem + OA1L))[si] = l[0];
            ((uint32_t*)(smem + OA1L))[si + 1] = l[1];
            split4(pv2[q], h, l);
            ((uint32_t*)(smem + OA2H))[si] = h[0];
            ((uint32_t*)(smem + OA2H))[si + 1] = h[1];
            ((uint32_t*)(smem + OA2L))[si] = l[0];
            ((uint32_t*)(smem + OA2L))[si + 1] = l[1];
        }

        // prefetch next chunk
        if (chunk + 1 < nch) {
            int k0n = (chunk + 1) << 5;
            int nbuf = OB_BASE + (buf ^ 1) * 4 * B_TILE_B;
            size_t ge = (size_t)(k0n + brow) * N + bn + bseg * 8;
#pragma unroll
            for (int t = 0; t < 4; t++)
                CP_ASYNC16(sb + nbuf + t * B_TILE_B + bso, gB[t] + ge);
            CP_COMMIT();
#pragma unroll
            for (int q = 0; q < 4; q++) {
                int gr = bm + arow[q];
                pv1[q] = make_float4(0.f, 0.f, 0.f, 0.f);
                pv2[q] = make_float4(0.f, 0.f, 0.f, 0.f);
                if (gr < M) {
                    pv1[q] = *(const float4*)(A1 + (size_t)gr * K + k0n + ak4[q]);
                    pv2[q] = *(const float4*)(A2 + (size_t)gr * K + k0n + ak4[q]);
                }
            }
            CP_WAIT(1);
        } else {
            CP_WAIT(0);
        }
        __syncthreads();

#pragma unroll
        for (int kk = 0; kk < 2; kk++) {
            uint32_t fa1h[2][4], fa1l[2][4], fa2h[2][4], fa2l[2][4];
#pragma unroll
            for (int mi = 0; mi < 2; mi++) {
                uint32_t aoff = (uint32_t)((wm * 32 + mi * 16 + (lane & 15)) * 80 +
                                           (lane >> 4) * 16 + kk * 32);
                LDSM_X4(fa1h[mi][0], fa1h[mi][1], fa1h[mi][2], fa1h[mi][3], sb + OA1H + aoff);
                LDSM_X4(fa1l[mi][0], fa1l[mi][1], fa1l[mi][2], fa1l[mi][3], sb + OA1L + aoff);
                LDSM_X4(fa2h[mi][0], fa2h[mi][1], fa2h[mi][2], fa2h[mi][3], sb + OA2H + aoff);
                LDSM_X4(fa2l[mi][0], fa2l[mi][1], fa2l[mi][2], fa2l[mi][3], sb + OA2L + aoff);
            }
            uint32_t fb1h[4][2], fb1l[4][2], fb2h[4][2], fb2l[4][2];
#pragma unroll
            for (int np = 0; np < 2; np++) {
                uint32_t boff = (uint32_t)((kk * 16 + (lane & 7) + ((lane >> 3) & 1) * 8) * 144 +
                                           wn * 64 + np * 32 + (lane >> 4) * 16);
                LDSM_X4T(fb1h[2 * np][0], fb1h[2 * np][1], fb1h[2 * np + 1][0], fb1h[2 * np + 1][1], sb + obuf + 0 * B_TILE_B + boff);
                LDSM_X4T(fb1l[2 * np][0], fb1l[2 * np][1], fb1l[2 * np + 1][0], fb1l[2 * np + 1][1], sb + obuf + 1 * B_TILE_B + boff);
                LDSM_X4T(fb2h[2 * np][0], fb2h[2 * np][1], fb2h[2 * np + 1][0], fb2h[2 * np + 1][1], sb + obuf + 2 * B_TILE_B + boff);
                LDSM_X4T(fb2l[2 * np][0], fb2l[2 * np][1], fb2l[2 * np + 1][0], fb2l[2 * np + 1][1], sb + obuf + 3 * B_TILE_B + boff);
            }
#pragma unroll
            for (int mi = 0; mi < 2; mi++)
#pragma unroll
                for (int nj = 0; nj < 4; nj++) {
                    MMA_BF16(acc[mi][nj], fa1h[mi], fb1h[nj]);
                    MMA_BF16(acc[mi][nj], fa1h[mi], fb1l[nj]);
                    MMA_BF16(acc[mi][nj], fa1l[mi], fb1h[nj]);
                    MMA_BF16(acc[mi][nj], fa2h[mi], fb2h[nj]);
                    MMA_BF16(acc[mi][nj], fa2h[mi], fb2l[nj]);
                    MMA_BF16(acc[mi][nj], fa2l[mi], fb2h[nj]);
                }
        }
        __syncthreads();
    }

    // epilogue
    int g = lane >> 2, c2 = (lane & 3) * 2;
#pragma unroll
    for (int mi = 0; mi < 2; mi++)
#pragma unroll
        for (int nj = 0; nj < 4; nj++) {
            int col = bn + wn * 32 + nj * 8 + c2;
            float2 bv = *(const float2*)(bias + col);
            int r0 = bm + wm * 32 + mi * 16 + g;
            if (r0 < M) {
                float2 o;
                o.x = fmaxf(acc[mi][nj][0] + bv.x, 0.f);
                o.y = fmaxf(acc[mi][nj][1] + bv.y, 0.f);
                *(float2*)(C + (size_t)r0 * N + col) = o;
            }
            int r1 = r0 + 8;
            if (r1 < M) {
                float2 o;
                o.x = fmaxf(acc[mi][nj][2] + bv.x, 0.f);
                o.y = fmaxf(acc[mi][nj][3] + bv.y, 0.f);
                *(float2*)(C + (size_t)r1 * N + col) = o;
            }
        }
}

// -------- layer 2: S = A@Bs + bias, T = A@Bt --------
__global__ void __launch_bounds__(256) k_mm_pair(
    const float* __restrict__ A,
    const __nv_bfloat16* __restrict__ Bsh, const __nv_bfloat16* __restrict__ Bsl,
    const __nv_bfloat16* __restrict__ Bth, const __nv_bfloat16* __restrict__ Btl,
    const float* __restrict__ bias, float* __restrict__ S, float* __restrict__ T,
    int M, int N, int K)
{
    extern __shared__ char smem[];
    const int OAH = 0, OAL = A_TILE_B;
    const int OB_BASE = 2 * A_TILE_B;
    uint32_t sb = smem_u32(smem);

    int tid = threadIdx.x, lane = tid & 31, wid = tid >> 5;
    int wm = wid & 3, wn = wid >> 2;
    int bm = blockIdx.y * 128, bn = blockIdx.x * 64;
    const int nch = K >> 5;

    int brow = tid >> 3, bseg = tid & 7;
    uint32_t bso = (uint32_t)(brow * 144 + bseg * 16);
    const __nv_bfloat16* gB[4] = {Bsh, Bsl, Bth, Btl};

    int arow[4], ak4[4];
#pragma unroll
    for (int q = 0; q < 4; q++) {
        int slot = tid + q * 256;
        arow[q] = slot >> 3;
        ak4[q] = (slot & 7) * 4;
    }

    float accS[2][4][4], accT[2][4][4];
#pragma unroll
    for (int i = 0; i < 2; i++)
#pragma unroll
        for (int j = 0; j < 4; j++)
#pragma unroll
            for (int q = 0; q < 4; q++) { accS[i][j][q] = 0.f; accT[i][j][q] = 0.f; }

    float4 pv[4];

    {
        size_t ge = (size_t)brow * N + bn + bseg * 8;
#pragma unroll
        for (int t = 0; t < 4; t++)
            CP_ASYNC16(sb + OB_BASE + t * B_TILE_B + bso, gB[t] + ge);
        CP_COMMIT();
#pragma unroll
        for (int q = 0; q < 4; q++) {
            int gr = bm + arow[q];
            pv[q] = make_float4(0.f, 0.f, 0.f, 0.f);
            if (gr < M) pv[q] = *(const float4*)(A + (size_t)gr * K + ak4[q]);
        }
    }

    for (int chunk = 0; chunk < nch; chunk++) {
        int buf = chunk & 1;
        int obuf = OB_BASE + buf * 4 * B_TILE_B;

#pragma unroll
        for (int q = 0; q < 4; q++) {
            uint32_t h[2], l[2];
            split4(pv[q], h, l);
            int si = arow[q] * 20 + (ak4[q] >> 1);
            ((uint32_t*)(smem + OAH))[si] = h[0];
            ((uint32_t*)(smem + OAH))[si + 1] = h[1];
            ((uint32_t*)(smem + OAL))[si] = l[0];
            ((uint32_t*)(smem + OAL))[si + 1] = l[1];
        }

        if (chunk + 1 < nch) {
            int k0n = (chunk + 1) << 5;
            int nbuf = OB_BASE + (buf ^ 1) * 4 * B_TILE_B;
            size_t ge = (size_t)(k0n + brow) * N + bn + bseg * 8;
#pragma unroll
            for (int t = 0; t < 4; t++)
                CP_ASYNC16(sb + nbuf + t * B_TILE_B + bso, gB[t] + ge);
            CP_COMMIT();
#pragma unroll
            for (int q = 0; q < 4; q++) {
                int gr = bm + arow[q];
                pv[q] = make_float4(0.f, 0.f, 0.f, 0.f);
                if (gr < M) pv[q] = *(const float4*)(A + (size_t)gr * K + k0n + ak4[q]);
            }
            CP_WAIT(1);
        } else {
            CP_WAIT(0);
        }
        __syncthreads();

#pragma unroll
        for (int kk = 0; kk < 2; kk++) {
            uint32_t fah[2][4], fal[2][4];
#pragma unroll
            for (int mi = 0; mi < 2; mi++) {
                uint32_t aoff = (uint32_t)((wm * 32 + mi * 16 + (lane & 15)) * 80 +
                                           (lane >> 4) * 16 + kk * 32);
                LDSM_X4(fah[mi][0], fah[mi][1], fah[mi][2], fah[mi][3], sb + OAH + aoff);
                LDSM_X4(fal[mi][0], fal[mi][1], fal[mi][2], fal[mi][3], sb + OAL + aoff);
            }
            uint32_t fbsh[4][2], fbsl[4][2], fbth[4][2], fbtl[4][2];
#pragma unroll
            for (int np = 0; np < 2; np++) {
                uint32_t boff = (uint32_t)((kk * 16 + (lane & 7) + ((lane >> 3) & 1) * 8) * 144 +
                                           wn * 64 + np * 32 + (lane >> 4) * 16);
                LDSM_X4T(fbsh[2 * np][0], fbsh[2 * np][1], fbsh[2 * np + 1][0], fbsh[2 * np + 1][1], sb + obuf + 0 * B_TILE_B + boff);
                LDSM_X4T(fbsl[2 * np][0], fbsl[2 * np][1], fbsl[2 * np + 1][0], fbsl[2 * np + 1][1], sb + obuf + 1 * B_TILE_B + boff);
                LDSM_X4T(fbth[2 * np][0], fbth[2 * np][1], fbth[2 * np + 1][0], fbth[2 * np + 1][1], sb + obuf + 2 * B_TILE_B + boff);
                LDSM_X4T(fbtl[2 * np][0], fbtl[2 * np][1], fbtl[2 * np + 1][0], fbtl[2 * np + 1][1], sb + obuf + 3 * B_TILE_B + boff);
            }
#pragma unroll
            for (int mi = 0; mi < 2; mi++)
#pragma unroll
                for (int nj = 0; nj < 4; nj++) {
                    MMA_BF16(accS[mi][nj], fah[mi], fbsh[nj]);
                    MMA_BF16(accS[mi][nj], fah[mi], fbsl[nj]);
                    MMA_BF16(accS[mi][nj], fal[mi], fbsh[nj]);
                    MMA_BF16(accT[mi][nj], fah[mi], fbth[nj]);
                    MMA_BF16(accT[mi][nj], fah[mi], fbtl[nj]);
                    MMA_BF16(accT[mi][nj], fal[mi], fbth[nj]);
                }
        }
        __syncthreads();
    }

    int g = lane >> 2, c2 = (lane & 3) * 2;
#pragma unroll
    for (int mi = 0; mi < 2; mi++)
#pragma unroll
        for (int nj = 0; nj < 4; nj++) {
            int col = bn + wn * 32 + nj * 8 + c2;
            float2 bv = *(const float2*)(bias + col);
            int r0 = bm + wm * 32 + mi * 16 + g;
            if (r0 < M) {
                float2 os = {accS[mi][nj][0] + bv.x, accS[mi][nj][1] + bv.y};
                *(float2*)(S + (size_t)r0 * N + col) = os;
                float2 ot = {accT[mi][nj][0], accT[mi][nj][1]};
                *(float2*)(T + (size_t)r0 * N + col) = ot;
            }
            int r1 = r0 + 8;
            if (r1 < M) {
                float2 os = {accS[mi][nj][2] + bv.x, accS[mi][nj][3] + bv.y};
                *(float2*)(S + (size_t)r1 * N + col) = os;
                float2 ot = {accT[mi][nj][2], accT[mi][nj][3]};
                *(float2*)(T + (size_t)r1 * N + col) = ot;
            }
        }
}

// ---------------- fused layer-2 aggregation + node scores (unrolled x2) ----------------
__global__ void k_agg2_scores(const float* __restrict__ Wp) {
    int warps_per_blk = blockDim.x >> 5;
    int n = blockIdx.x * warps_per_blk + (threadIdx.x >> 5);
    if (n >= N_NODES) return;
    int lane = threadIdx.x & 31;
    int beg = g_rowptr[n], end = g_rowptr[n + 1];

    float4 acc0 = {0.f, 0.f, 0.f, 0.f};
    float4 acc1 = {0.f, 0.f, 0.f, 0.f};
    int j = beg;
    for (; j + 1 < end; j += 2) {
        int s0 = g_csr_src[j];
        int s1 = g_csr_src[j + 1];
        float4 v0 = __ldg(&((const float4*)(g_t2 + (size_t)s0 * 128))[lane]);
        float4 v1 = __ldg(&((const float4*)(g_t2 + (size_t)s1 * 128))[lane]);
        acc0.x += v0.x; acc0.y += v0.y; acc0.z += v0.z; acc0.w += v0.w;
        acc1.x += v1.x; acc1.y += v1.y; acc1.z += v1.z; acc1.w += v1.w;
    }
    if (j < end) {
        int s0 = g_csr_src[j];
        float4 v0 = __ldg(&((const float4*)(g_t2 + (size_t)s0 * 128))[lane]);
        acc0.x += v0.x; acc0.y += v0.y; acc0.z += v0.z; acc0.w += v0.w;
    }
    acc0.x += acc1.x; acc0.y += acc1.y; acc0.z += acc1.z; acc0.w += acc1.w;
    int deg = end - beg;
    float inv = (deg > 0) ? 1.f / (float)deg : 0.f;
    float4 sv = ((const float4*)(g_s2 + (size_t)n * 128))[lane];
    float4 h;
    h.x = sv.x + acc0.x * inv;
    h.y = sv.y + acc0.y * inv;
    h.z = sv.z + acc0.z * inv;
    h.w = sv.w + acc0.w * inv;

    float4 wa = __ldg(&((const float4*)Wp)[lane]);
    float4 wb = __ldg(&((const float4*)Wp)[lane + 32]);
    float a = h.x * wa.x + h.y * wa.y + h.z * wa.z + h.w * wa.w;
    float b = h.x * wb.x + h.y * wb.y + h.z * wb.z + h.w * wb.w;
#pragma unroll
    for (int off = 16; off; off >>= 1) {
        a += __shfl_down_sync(0xFFFFFFFFu, a, off);
        b += __shfl_down_sync(0xFFFFFFFFu, b, off);
    }
    if (lane == 0) { g_sA[n] = a; g_sB[n] = b; }
}

__global__ void k_edge_scores(const int* __restrict__ psrc, const int* __restrict__ pdst,
                              const int* __restrict__ nsrc, const int* __restrict__ ndst,
                              const float* __restrict__ bp, float* __restrict__ out,
                              int EP, int EN) {
    int i = blockIdx.x * blockDim.x + threadIdx.x;
    float b = bp[0];
    if (i < EP) {
        out[i] = g_sA[psrc[i]] + g_sB[pdst[i]] + b;
    } else if (i < EP + EN) {
        int j = i - EP;
        out[i] = g_sA[nsrc[j]] + g_sB[ndst[j]] + b;
    }
}

// ---------------- launch ----------------
extern "C" void kernel_launch(void* const* d_in, const int* in_sizes, int n_in,
                              void* d_out, int out_size) {
    const float* x    = (const float*)d_in[0];
    const int* msrc   = (const int*)d_in[1];
    const int* mdst   = (const int*)d_in[2];
    const int* psrc   = (const int*)d_in[3];
    const int* pdst   = (const int*)d_in[4];
    const int* nsrc   = (const int*)d_in[5];
    const int* ndst   = (const int*)d_in[6];
    const float* W1s  = (const float*)d_in[7];
    const float* W1n  = (const float*)d_in[8];
    const float* b1   = (const float*)d_in[9];
    const float* W2s  = (const float*)d_in[10];
    const float* W2n  = (const float*)d_in[11];
    const float* b2   = (const float*)d_in[12];
    const float* Wp   = (const float*)d_in[13];
    const float* bp   = (const float*)d_in[14];
    float* out = (float*)d_out;

    int E  = in_sizes[1];
    int EP = in_sizes[3];
    int EN = in_sizes[5];

    float *p_neigh1, *p_h1, *p_s2, *p_t2;
    cudaGetSymbolAddress((void**)&p_neigh1, g_neigh1);
    cudaGetSymbolAddress((void**)&p_h1,     g_h1);
    cudaGetSymbolAddress((void**)&p_s2,     g_s2);
    cudaGetSymbolAddress((void**)&p_t2,     g_t2);

    __nv_bfloat16 *w1sh, *w1sl, *w1nh, *w1nl, *w2sh, *w2sl, *w2nh, *w2nl;
    cudaGetSymbolAddress((void**)&w1sh, g_w1s_h);
    cudaGetSymbolAddress((void**)&w1sl, g_w1s_l);
    cudaGetSymbolAddress((void**)&w1nh, g_w1n_h);
    cudaGetSymbolAddress((void**)&w1nl, g_w1n_l);
    cudaGetSymbolAddress((void**)&w2sh, g_w2s_h);
    cudaGetSymbolAddress((void**)&w2sl, g_w2s_l);
    cudaGetSymbolAddress((void**)&w2nh, g_w2n_h);
    cudaGetSymbolAddress((void**)&w2nl, g_w2n_l);

    const int SMEM_DUAL = 4 * A_TILE_B + 2 * 4 * B_TILE_B;  // 77824
    const int SMEM_PAIR = 2 * A_TILE_B + 2 * 4 * B_TILE_B;  // 57344
    cudaFuncSetAttribute(k_mm_dual, cudaFuncAttributeMaxDynamicSharedMemorySize, SMEM_DUAL);
    cudaFuncSetAttribute(k_mm_pair, cudaFuncAttributeMaxDynamicSharedMemorySize, SMEM_PAIR);

    // CSR build
    k_zero_cnt<<<(N_NODES + 255) / 256, 256>>>();
    k_hist<<<(E + 255) / 256, 256>>>(mdst, E);
    k_scan<<<1, 1024>>>();
    k_fill<<<(E + 255) / 256, 256>>>(msrc, mdst, E);

    // weight split (single launch, 4 matrices)
    k_wprep_all<<<(4 * 32768 + 255) / 256, 256>>>(W1s, W1n, W2s, W2n);

    // layer 1
    k_agg128<<<(N_NODES + 7) / 8, 256>>>(x, p_neigh1);
    {
        dim3 grid(D_HID / 64, (N_NODES + 127) / 128);
        k_mm_dual<<<grid, 256, SMEM_DUAL>>>(x, p_neigh1, w1sh, w1sl, w1nh, w1nl,
                                            b1, p_h1, N_NODES, D_HID, D_IN);
    }
    // layer 2: project then aggregate
    {
        dim3 grid(D_OUT / 64, (N_NODES + 127) / 128);
        k_mm_pair<<<grid, 256, SMEM_PAIR>>>(p_h1, w2sh, w2sl, w2nh, w2nl,
                                            b2, p_s2, p_t2, N_NODES, D_OUT, D_HID);
    }
    k_agg2_scores<<<(N_NODES + 7) / 8, 256>>>(Wp);

    // edge scoring
    k_edge_scores<<<(EP + EN + 255) / 256, 256>>>(psrc, pdst, nsrc, ndst, bp, out, EP, EN);
}

// round 7
// speedup vs baseline: 1.0405x; 1.0405x over previous
#include <cuda_runtime.h>
#include <cuda_bf16.h>
#include <cstdint>

#define N_NODES 50000
#define MAX_E   800000
#define D_IN    128
#define D_HID   256
#define D_OUT   128

// ---------------- scratch (static device globals; no allocation) ----------------
__device__ float g_neigh1[(size_t)N_NODES * D_IN];
__device__ float g_h1[(size_t)N_NODES * D_HID];
__device__ float g_s2[(size_t)N_NODES * D_OUT];
__device__ float g_t2[(size_t)N_NODES * D_OUT];
__device__ float g_sA[N_NODES];
__device__ float g_sB[N_NODES];
__device__ int   g_cnt[N_NODES];
__device__ int   g_rowptr[N_NODES + 1];
__device__ int   g_cursor[N_NODES];
__device__ int   g_csr_src[MAX_E];

// pre-split bf16 weights, same (K,N) layout as the fp32 originals
__device__ __nv_bfloat16 g_w1s_h[D_IN * D_HID], g_w1s_l[D_IN * D_HID];
__device__ __nv_bfloat16 g_w1n_h[D_IN * D_HID], g_w1n_l[D_IN * D_HID];
__device__ __nv_bfloat16 g_w2s_h[D_HID * D_OUT], g_w2s_l[D_HID * D_OUT];
__device__ __nv_bfloat16 g_w2n_h[D_HID * D_OUT], g_w2n_l[D_HID * D_OUT];

// ---------------- helpers ----------------
__device__ __forceinline__ uint32_t smem_u32(const void* p) {
    uint32_t a;
    asm("{ .reg .u64 t; cvta.to.shared.u64 t, %1; cvt.u32.u64 %0, t; }" : "=r"(a) : "l"(p));
    return a;
}
__device__ __forceinline__ uint32_t bpack(__nv_bfloat16 a, __nv_bfloat16 b) {
    return (uint32_t)__bfloat16_as_ushort(a) | ((uint32_t)__bfloat16_as_ushort(b) << 16);
}
__device__ __forceinline__ void split4(float4 v, uint32_t* h, uint32_t* l) {
    __nv_bfloat16 hx = __float2bfloat16_rn(v.x);
    __nv_bfloat16 hy = __float2bfloat16_rn(v.y);
    __nv_bfloat16 hz = __float2bfloat16_rn(v.z);
    __nv_bfloat16 hw = __float2bfloat16_rn(v.w);
    h[0] = bpack(hx, hy);
    h[1] = bpack(hz, hw);
    __nv_bfloat16 lx = __float2bfloat16_rn(v.x - __bfloat162float(hx));
    __nv_bfloat16 ly = __float2bfloat16_rn(v.y - __bfloat162float(hy));
    __nv_bfloat16 lz = __float2bfloat16_rn(v.z - __bfloat162float(hz));
    __nv_bfloat16 lw = __float2bfloat16_rn(v.w - __bfloat162float(hw));
    l[0] = bpack(lx, ly);
    l[1] = bpack(lz, lw);
}

#define LDSM_X4(r0, r1, r2, r3, addr) \
    asm volatile("ldmatrix.sync.aligned.m8n8.x4.shared.b16 {%0,%1,%2,%3}, [%4];" \
                 : "=r"(r0), "=r"(r1), "=r"(r2), "=r"(r3) : "r"(addr))
#define LDSM_X4T(r0, r1, r2, r3, addr) \
    asm volatile("ldmatrix.sync.aligned.m8n8.x4.trans.shared.b16 {%0,%1,%2,%3}, [%4];" \
                 : "=r"(r0), "=r"(r1), "=r"(r2), "=r"(r3) : "r"(addr))
#define MMA_BF16(c, a, b) \
    asm volatile("mma.sync.aligned.m16n8k16.row.col.f32.bf16.bf16.f32 " \
                 "{%0,%1,%2,%3}, {%4,%5,%6,%7}, {%8,%9}, {%0,%1,%2,%3};" \
                 : "+f"((c)[0]), "+f"((c)[1]), "+f"((c)[2]), "+f"((c)[3]) \
                 : "r"((a)[0]), "r"((a)[1]), "r"((a)[2]), "r"((a)[3]), \
                   "r"((b)[0]), "r"((b)[1]))

// ---------------- CSR build ----------------
__global__ void k_zero_cnt() {
    int i = blockIdx.x * blockDim.x + threadIdx.x;
    if (i < N_NODES) g_cnt[i] = 0;
}
__global__ void k_hist(const int* __restrict__ dst, int E) {
    int e = blockIdx.x * blockDim.x + threadIdx.x;
    if (e < E) atomicAdd(&g_cnt[dst[e]], 1);
}
__global__ void k_scan() {
    const int T = 1024;
    const int C = (N_NODES + T - 1) / T;
    __shared__ int partial[T];
    int t = threadIdx.x;
    int base = t * C;
    int s = 0;
    for (int i = 0; i < C; i++) {
        int idx = base + i;
        if (idx < N_NODES) s += g_cnt[idx];
    }
    partial[t] = s;
    __syncthreads();
    for (int off = 1; off < T; off <<= 1) {
        int v = (t >= off) ? partial[t - off] : 0;
        __syncthreads();
        partial[t] += v;
        __syncthreads();
    }
    int run = partial[t] - s;
    for (int i = 0; i < C; i++) {
        int idx = base + i;
        if (idx < N_NODES) {
            g_rowptr[idx] = run;
            g_cursor[idx] = run;
            run += g_cnt[idx];
        }
    }
    if (t == 0) g_rowptr[N_NODES] = partial[T - 1];
}
__global__ void k_fill(const int* __restrict__ src, const int* __restrict__ dst, int E) {
    int e = blockIdx.x * blockDim.x + threadIdx.x;
    if (e < E) {
        int d = dst[e];
        int pos = atomicAdd(&g_cursor[d], 1);
        g_csr_src[pos] = src[e];
    }
}

// ---------------- layer-1 aggregation (unrolled x4, 4 accumulators) ----------------
__global__ void k_agg128(const float* __restrict__ feat, float* __restrict__ out) {
    int warps_per_blk = blockDim.x >> 5;
    int n = blockIdx.x * warps_per_blk + (threadIdx.x >> 5);
    if (n >= N_NODES) return;
    int lane = threadIdx.x & 31;
    int beg = g_rowptr[n], end = g_rowptr[n + 1];

    float4 a0 = {0.f, 0.f, 0.f, 0.f};
    float4 a1 = {0.f, 0.f, 0.f, 0.f};
    float4 a2 = {0.f, 0.f, 0.f, 0.f};
    float4 a3 = {0.f, 0.f, 0.f, 0.f};
    int j = beg;
    for (; j + 3 < end; j += 4) {
        int s0 = g_csr_src[j];
        int s1 = g_csr_src[j + 1];
        int s2 = g_csr_src[j + 2];
        int s3 = g_csr_src[j + 3];
        float4 v0 = __ldg(&((const float4*)(feat + (size_t)s0 * 128))[lane]);
        float4 v1 = __ldg(&((const float4*)(feat + (size_t)s1 * 128))[lane]);
        float4 v2 = __ldg(&((const float4*)(feat + (size_t)s2 * 128))[lane]);
        float4 v3 = __ldg(&((const float4*)(feat + (size_t)s3 * 128))[lane]);
        a0.x += v0.x; a0.y += v0.y; a0.z += v0.z; a0.w += v0.w;
        a1.x += v1.x; a1.y += v1.y; a1.z += v1.z; a1.w += v1.w;
        a2.x += v2.x; a2.y += v2.y; a2.z += v2.z; a2.w += v2.w;
        a3.x += v3.x; a3.y += v3.y; a3.z += v3.z; a3.w += v3.w;
    }
    for (; j < end; j++) {
        int s0 = g_csr_src[j];
        float4 v0 = __ldg(&((const float4*)(feat + (size_t)s0 * 128))[lane]);
        a0.x += v0.x; a0.y += v0.y; a0.z += v0.z; a0.w += v0.w;
    }
    a0.x += a1.x + a2.x + a3.x;
    a0.y += a1.y + a2.y + a3.y;
    a0.z += a1.z + a2.z + a3.z;
    a0.w += a1.w + a2.w + a3.w;
    int deg = end - beg;
    float inv = (deg > 0) ? 1.f / (float)deg : 0.f;
    float4 o = {a0.x * inv, a0.y * inv, a0.z * inv, a0.w * inv};
    ((float4*)(out + (size_t)n * 128))[lane] = o;
}

// ---------------- weight split: all 4 matrices, one launch ----------------
__global__ void k_wprep_all(
    const float* __restrict__ W1s, const float* __restrict__ W1n,
    const float* __restrict__ W2s, const float* __restrict__ W2n)
{
    int i = blockIdx.x * blockDim.x + threadIdx.x;
    if (i >= 4 * 32768) return;
    int a = i >> 15, r = i & 32767;
    const float* W = (a == 0) ? W1s : (a == 1) ? W1n : (a == 2) ? W2s : W2n;
    __nv_bfloat16* hi = (a == 0) ? g_w1s_h : (a == 1) ? g_w1n_h : (a == 2) ? g_w2s_h : g_w2n_h;
    __nv_bfloat16* lo = (a == 0) ? g_w1s_l : (a == 1) ? g_w1n_l : (a == 2) ? g_w2s_l : g_w2n_l;
    float w = W[r];
    __nv_bfloat16 h = __float2bfloat16_rn(w);
    hi[r] = h;
    lo[r] = __float2bfloat16_rn(w - __bfloat162float(h));
}

// ================= bf16x3 mma.sync GEMMs (round-5 structure: single-buffered) =================
// CTA tile 128(M) x 64(N), BK=32. 8 warps: wm=wid&3 (M), wn=wid>>2 (N).
// SMEM: A tiles 128 rows x 40 bf16 (80B row = 16x5); B tiles 32 rows x 72 bf16 (144B row = 16x9).
#define A_TILE_B 10240
#define B_TILE_B 4608

// -------- layer 1: C = relu(A1@B1 + A2@B2 + bias) --------
__global__ void __launch_bounds__(256) k_mm_dual(
    const float* __restrict__ A1, const float* __restrict__ A2,
    const __nv_bfloat16* __restrict__ B1h, const __nv_bfloat16* __restrict__ B1l,
    const __nv_bfloat16* __restrict__ B2h, const __nv_bfloat16* __restrict__ B2l,
    const float* __restrict__ bias, float* __restrict__ C,
    int M, int N, int K)
{
    extern __shared__ char smem[];
    const int OA1H = 0, OA1L = A_TILE_B, OA2H = 2 * A_TILE_B, OA2L = 3 * A_TILE_B;
    const int OB1H = 4 * A_TILE_B, OB1L = OB1H + B_TILE_B;
    const int OB2H = OB1H + 2 * B_TILE_B, OB2L = OB1H + 3 * B_TILE_B;
    uint32_t sb = smem_u32(smem);

    int tid = threadIdx.x, lane = tid & 31, wid = tid >> 5;
    int wm = wid & 3, wn = wid >> 2;
    int bm = blockIdx.y * 128, bn = blockIdx.x * 64;

    float acc[2][4][4];
#pragma unroll
    for (int i = 0; i < 2; i++)
#pragma unroll
        for (int j = 0; j < 4; j++)
#pragma unroll
            for (int q = 0; q < 4; q++) acc[i][j][q] = 0.f;

    for (int k0 = 0; k0 < K; k0 += 32) {
        // stage A (split on the fly)
#pragma unroll
        for (int q = 0; q < 4; q++) {
            int slot = tid + q * 256;
            int row = slot >> 3, k4 = (slot & 7) * 4;
            int gr = bm + row;
            float4 v1 = {0.f, 0.f, 0.f, 0.f}, v2 = {0.f, 0.f, 0.f, 0.f};
            if (gr < M) {
                v1 = *(const float4*)(A1 + (size_t)gr * K + k0 + k4);
                v2 = *(const float4*)(A2 + (size_t)gr * K + k0 + k4);
            }
            uint32_t h[2], l[2];
            int si = row * 20 + (k4 >> 1);
            split4(v1, h, l);
            ((uint32_t*)(smem + OA1H))[si] = h[0];
            ((uint32_t*)(smem + OA1H))[si + 1] = h[1];
            ((uint32_t*)(smem + OA1L))[si] = l[0];
            ((uint32_t*)(smem + OA1L))[si + 1] = l[1];
            split4(v2, h, l);
            ((uint32_t*)(smem + OA2H))[si] = h[0];
            ((uint32_t*)(smem + OA2H))[si + 1] = h[1];
            ((uint32_t*)(smem + OA2L))[si] = l[0];
            ((uint32_t*)(smem + OA2L))[si + 1] = l[1];
        }
        // stage B (pre-split)
#pragma unroll
        for (int q = 0; q < 4; q++) {
            int slot = tid + q * 256;
            int k = slot >> 5, n2 = slot & 31;
            size_t gu = (((size_t)(k0 + k) * N + bn) >> 1) + n2;
            int si = k * 36 + n2;
            ((uint32_t*)(smem + OB1H))[si] = ((const uint32_t*)B1h)[gu];
            ((uint32_t*)(smem + OB1L))[si] = ((const uint32_t*)B1l)[gu];
            ((uint32_t*)(smem + OB2H))[si] = ((const uint32_t*)B2h)[gu];
            ((uint32_t*)(smem + OB2L))[si] = ((const uint32_t*)B2l)[gu];
        }
        __syncthreads();

#pragma unroll
        for (int kk = 0; kk < 2; kk++) {
            uint32_t fa1h[2][4], fa1l[2][4], fa2h[2][4], fa2l[2][4];
#pragma unroll
            for (int mi = 0; mi < 2; mi++) {
                uint32_t aoff = (uint32_t)((wm * 32 + mi * 16 + (lane & 15)) * 80 +
                                           (lane >> 4) * 16 + kk * 32);
                LDSM_X4(fa1h[mi][0], fa1h[mi][1], fa1h[mi][2], fa1h[mi][3], sb + OA1H + aoff);
                LDSM_X4(fa1l[mi][0], fa1l[mi][1], fa1l[mi][2], fa1l[mi][3], sb + OA1L + aoff);
                LDSM_X4(fa2h[mi][0], fa2h[mi][1], fa2h[mi][2], fa2h[mi][3], sb + OA2H + aoff);
                LDSM_X4(fa2l[mi][0], fa2l[mi][1], fa2l[mi][2], fa2l[mi][3], sb + OA2L + aoff);
            }
            uint32_t fb1h[4][2], fb1l[4][2], fb2h[4][2], fb2l[4][2];
#pragma unroll
            for (int np = 0; np < 2; np++) {
                uint32_t boff = (uint32_t)((kk * 16 + (lane & 7) + ((lane >> 3) & 1) * 8) * 144 +
                                           wn * 64 + np * 32 + (lane >> 4) * 16);
                LDSM_X4T(fb1h[2 * np][0], fb1h[2 * np][1], fb1h[2 * np + 1][0], fb1h[2 * np + 1][1], sb + OB1H + boff);
                LDSM_X4T(fb1l[2 * np][0], fb1l[2 * np][1], fb1l[2 * np + 1][0], fb1l[2 * np + 1][1], sb + OB1L + boff);
                LDSM_X4T(fb2h[2 * np][0], fb2h[2 * np][1], fb2h[2 * np + 1][0], fb2h[2 * np + 1][1], sb + OB2H + boff);
                LDSM_X4T(fb2l[2 * np][0], fb2l[2 * np][1], fb2l[2 * np + 1][0], fb2l[2 * np + 1][1], sb + OB2L + boff);
            }
#pragma unroll
            for (int mi = 0; mi < 2; mi++)
#pragma unroll
                for (int nj = 0; nj < 4; nj++) {
                    MMA_BF16(acc[mi][nj], fa1h[mi], fb1h[nj]);
                    MMA_BF16(acc[mi][nj], fa1h[mi], fb1l[nj]);
                    MMA_BF16(acc[mi][nj], fa1l[mi], fb1h[nj]);
                    MMA_BF16(acc[mi][nj], fa2h[mi], fb2h[nj]);
                    MMA_BF16(acc[mi][nj], fa2h[mi], fb2l[nj]);
                    MMA_BF16(acc[mi][nj], fa2l[mi], fb2h[nj]);
                }
        }
        __syncthreads();
    }

    // epilogue
    int g = lane >> 2, c2 = (lane & 3) * 2;
#pragma unroll
    for (int mi = 0; mi < 2; mi++)
#pragma unroll
        for (int nj = 0; nj < 4; nj++) {
            int col = bn + wn * 32 + nj * 8 + c2;
            float2 bv = *(const float2*)(bias + col);
            int r0 = bm + wm * 32 + mi * 16 + g;
            if (r0 < M) {
                float2 o;
                o.x = fmaxf(acc[mi][nj][0] + bv.x, 0.f);
                o.y = fmaxf(acc[mi][nj][1] + bv.y, 0.f);
                *(float2*)(C + (size_t)r0 * N + col) = o;
            }
            int r1 = r0 + 8;
            if (r1 < M) {
                float2 o;
                o.x = fmaxf(acc[mi][nj][2] + bv.x, 0.f);
                o.y = fmaxf(acc[mi][nj][3] + bv.y, 0.f);
                *(float2*)(C + (size_t)r1 * N + col) = o;
            }
        }
}

// -------- layer 2: S = A@Bs + bias, T = A@Bt --------
__global__ void __launch_bounds__(256) k_mm_pair(
    const float* __restrict__ A,
    const __nv_bfloat16* __restrict__ Bsh, const __nv_bfloat16* __restrict__ Bsl,
    const __nv_bfloat16* __restrict__ Bth, const __nv_bfloat16* __restrict__ Btl,
    const float* __restrict__ bias, float* __restrict__ S, float* __restrict__ T,
    int M, int N, int K)
{
    extern __shared__ char smem[];
    const int OAH = 0, OAL = A_TILE_B;
    const int OBSH = 2 * A_TILE_B, OBSL = OBSH + B_TILE_B;
    const int OBTH = OBSH + 2 * B_TILE_B, OBTL = OBSH + 3 * B_TILE_B;
    uint32_t sb = smem_u32(smem);

    int tid = threadIdx.x, lane = tid & 31, wid = tid >> 5;
    int wm = wid & 3, wn = wid >> 2;
    int bm = blockIdx.y * 128, bn = blockIdx.x * 64;

    float accS[2][4][4], accT[2][4][4];
#pragma unroll
    for (int i = 0; i < 2; i++)
#pragma unroll
        for (int j = 0; j < 4; j++)
#pragma unroll
            for (int q = 0; q < 4; q++) { accS[i][j][q] = 0.f; accT[i][j][q] = 0.f; }

    for (int k0 = 0; k0 < K; k0 += 32) {
#pragma unroll
        for (int q = 0; q < 4; q++) {
            int slot = tid + q * 256;
            int row = slot >> 3, k4 = (slot & 7) * 4;
            int gr = bm + row;
            float4 v = {0.f, 0.f, 0.f, 0.f};
            if (gr < M) v = *(const float4*)(A + (size_t)gr * K + k0 + k4);
            uint32_t h[2], l[2];
            split4(v, h, l);
            int si = row * 20 + (k4 >> 1);
            ((uint32_t*)(smem + OAH))[si] = h[0];
            ((uint32_t*)(smem + OAH))[si + 1] = h[1];
            ((uint32_t*)(smem + OAL))[si] = l[0];
            ((uint32_t*)(smem + OAL))[si + 1] = l[1];
        }
#pragma unroll
        for (int q = 0; q < 4; q++) {
            int slot = tid + q * 256;
            int k = slot >> 5, n2 = slot & 31;
            size_t gu = (((size_t)(k0 + k) * N + bn) >> 1) + n2;
            int si = k * 36 + n2;
            ((uint32_t*)(smem + OBSH))[si] = ((const uint32_t*)Bsh)[gu];
            ((uint32_t*)(smem + OBSL))[si] = ((const uint32_t*)Bsl)[gu];
            ((uint32_t*)(smem + OBTH))[si] = ((const uint32_t*)Bth)[gu];
            ((uint32_t*)(smem + OBTL))[si] = ((const uint32_t*)Btl)[gu];
        }
        __syncthreads();

#pragma unroll
        for (int kk = 0; kk < 2; kk++) {
            uint32_t fah[2][4], fal[2][4];
#pragma unroll
            for (int mi = 0; mi < 2; mi++) {
                uint32_t aoff = (uint32_t)((wm * 32 + mi * 16 + (lane & 15)) * 80 +
                                           (lane >> 4) * 16 + kk * 32);
                LDSM_X4(fah[mi][0], fah[mi][1], fah[mi][2], fah[mi][3], sb + OAH + aoff);
                LDSM_X4(fal[mi][0], fal[mi][1], fal[mi][2], fal[mi][3], sb + OAL + aoff);
            }
            uint32_t fbsh[4][2], fbsl[4][2], fbth[4][2], fbtl[4][2];
#pragma unroll
            for (int np = 0; np < 2; np++) {
                uint32_t boff = (uint32_t)((kk * 16 + (lane & 7) + ((lane >> 3) & 1) * 8) * 144 +
                                           wn * 64 + np * 32 + (lane >> 4) * 16);
                LDSM_X4T(fbsh[2 * np][0], fbsh[2 * np][1], fbsh[2 * np + 1][0], fbsh[2 * np + 1][1], sb + OBSH + boff);
                LDSM_X4T(fbsl[2 * np][0], fbsl[2 * np][1], fbsl[2 * np + 1][0], fbsl[2 * np + 1][1], sb + OBSL + boff);
                LDSM_X4T(fbth[2 * np][0], fbth[2 * np][1], fbth[2 * np + 1][0], fbth[2 * np + 1][1], sb + OBTH + boff);
                LDSM_X4T(fbtl[2 * np][0], fbtl[2 * np][1], fbtl[2 * np + 1][0], fbtl[2 * np + 1][1], sb + OBTL + boff);
            }
#pragma unroll
            for (int mi = 0; mi < 2; mi++)
#pragma unroll
                for (int nj = 0; nj < 4; nj++) {
                    MMA_BF16(accS[mi][nj], fah[mi], fbsh[nj]);
                    MMA_BF16(accS[mi][nj], fah[mi], fbsl[nj]);
                    MMA_BF16(accS[mi][nj], fal[mi], fbsh[nj]);
                    MMA_BF16(accT[mi][nj], fah[mi], fbth[nj]);
                    MMA_BF16(accT[mi][nj], fah[mi], fbtl[nj]);
                    MMA_BF16(accT[mi][nj], fal[mi], fbth[nj]);
                }
        }
        __syncthreads();
    }

    int g = lane >> 2, c2 = (lane & 3) * 2;
#pragma unroll
    for (int mi = 0; mi < 2; mi++)
#pragma unroll
        for (int nj = 0; nj < 4; nj++) {
            int col = bn + wn * 32 + nj * 8 + c2;
            float2 bv = *(const float2*)(bias + col);
            int r0 = bm + wm * 32 + mi * 16 + g;
            if (r0 < M) {
                float2 os = {accS[mi][nj][0] + bv.x, accS[mi][nj][1] + bv.y};
                *(float2*)(S + (size_t)r0 * N + col) = os;
                float2 ot = {accT[mi][nj][0], accT[mi][nj][1]};
                *(float2*)(T + (size_t)r0 * N + col) = ot;
            }
            int r1 = r0 + 8;
            if (r1 < M) {
                float2 os = {accS[mi][nj][2] + bv.x, accS[mi][nj][3] + bv.y};
                *(float2*)(S + (size_t)r1 * N + col) = os;
                float2 ot = {accT[mi][nj][2], accT[mi][nj][3]};
                *(float2*)(T + (size_t)r1 * N + col) = ot;
            }
        }
}

// ---------------- fused layer-2 aggregation + node scores (unrolled x4) ----------------
__global__ void k_agg2_scores(const float* __restrict__ Wp) {
    int warps_per_blk = blockDim.x >> 5;
    int n = blockIdx.x * warps_per_blk + (threadIdx.x >> 5);
    if (n >= N_NODES) return;
    int lane = threadIdx.x & 31;
    int beg = g_rowptr[n], end = g_rowptr[n + 1];

    float4 a0 = {0.f, 0.f, 0.f, 0.f};
    float4 a1 = {0.f, 0.f, 0.f, 0.f};
    float4 a2 = {0.f, 0.f, 0.f, 0.f};
    float4 a3 = {0.f, 0.f, 0.f, 0.f};
    int j = beg;
    for (; j + 3 < end; j += 4) {
        int s0 = g_csr_src[j];
        int s1 = g_csr_src[j + 1];
        int s2 = g_csr_src[j + 2];
        int s3 = g_csr_src[j + 3];
        float4 v0 = __ldg(&((const float4*)(g_t2 + (size_t)s0 * 128))[lane]);
        float4 v1 = __ldg(&((const float4*)(g_t2 + (size_t)s1 * 128))[lane]);
        float4 v2 = __ldg(&((const float4*)(g_t2 + (size_t)s2 * 128))[lane]);
        float4 v3 = __ldg(&((const float4*)(g_t2 + (size_t)s3 * 128))[lane]);
        a0.x += v0.x; a0.y += v0.y; a0.z += v0.z; a0.w += v0.w;
        a1.x += v1.x; a1.y += v1.y; a1.z += v1.z; a1.w += v1.w;
        a2.x += v2.x; a2.y += v2.y; a2.z += v2.z; a2.w += v2.w;
        a3.x += v3.x; a3.y += v3.y; a3.z += v3.z; a3.w += v3.w;
    }
    for (; j < end; j++) {
        int s0 = g_csr_src[j];
        float4 v0 = __ldg(&((const float4*)(g_t2 + (size_t)s0 * 128))[lane]);
        a0.x += v0.x; a0.y += v0.y; a0.z += v0.z; a0.w += v0.w;
    }
    a0.x += a1.x + a2.x + a3.x;
    a0.y += a1.y + a2.y + a3.y;
    a0.z += a1.z + a2.z + a3.z;
    a0.w += a1.w + a2.w + a3.w;
    int deg = end - beg;
    float inv = (deg > 0) ? 1.f / (float)deg : 0.f;
    float4 sv = ((const float4*)(g_s2 + (size_t)n * 128))[lane];
    float4 h;
    h.x = sv.x + a0.x * inv;
    h.y = sv.y + a0.y * inv;
    h.z = sv.z + a0.z * inv;
    h.w = sv.w + a0.w * inv;

    float4 wa = __ldg(&((const float4*)Wp)[lane]);
    float4 wb = __ldg(&((const float4*)Wp)[lane + 32]);
    float a = h.x * wa.x + h.y * wa.y + h.z * wa.z + h.w * wa.w;
    float b = h.x * wb.x + h.y * wb.y + h.z * wb.z + h.w * wb.w;
#pragma unroll
    for (int off = 16; off; off >>= 1) {
        a += __shfl_down_sync(0xFFFFFFFFu, a, off);
        b += __shfl_down_sync(0xFFFFFFFFu, b, off);
    }
    if (lane == 0) { g_sA[n] = a; g_sB[n] = b; }
}

__global__ void k_edge_scores(const int* __restrict__ psrc, const int* __restrict__ pdst,
                              const int* __restrict__ nsrc, const int* __restrict__ ndst,
                              const float* __restrict__ bp, float* __restrict__ out,
                              int EP, int EN) {
    int i = blockIdx.x * blockDim.x + threadIdx.x;
    float b = bp[0];
    if (i < EP) {
        out[i] = g_sA[psrc[i]] + g_sB[pdst[i]] + b;
    } else if (i < EP + EN) {
        int j = i - EP;
        out[i] = g_sA[nsrc[j]] + g_sB[ndst[j]] + b;
    }
}

// ---------------- launch ----------------
extern "C" void kernel_launch(void* const* d_in, const int* in_sizes, int n_in,
                              void* d_out, int out_size) {
    const float* x    = (const float*)d_in[0];
    const int* msrc   = (const int*)d_in[1];
    const int* mdst   = (const int*)d_in[2];
    const int* psrc   = (const int*)d_in[3];
    const int* pdst   = (const int*)d_in[4];
    const int* nsrc   = (const int*)d_in[5];
    const int* ndst   = (const int*)d_in[6];
    const float* W1s  = (const float*)d_in[7];
    const float* W1n  = (const float*)d_in[8];
    const float* b1   = (const float*)d_in[9];
    const float* W2s  = (const float*)d_in[10];
    const float* W2n  = (const float*)d_in[11];
    const float* b2   = (const float*)d_in[12];
    const float* Wp   = (const float*)d_in[13];
    const float* bp   = (const float*)d_in[14];
    float* out = (float*)d_out;

    int E  = in_sizes[1];
    int EP = in_sizes[3];
    int EN = in_sizes[5];

    float *p_neigh1, *p_h1, *p_s2, *p_t2;
    cudaGetSymbolAddress((void**)&p_neigh1, g_neigh1);
    cudaGetSymbolAddress((void**)&p_h1,     g_h1);
    cudaGetSymbolAddress((void**)&p_s2,     g_s2);
    cudaGetSymbolAddress((void**)&p_t2,     g_t2);

    __nv_bfloat16 *w1sh, *w1sl, *w1nh, *w1nl, *w2sh, *w2sl, *w2nh, *w2nl;
    cudaGetSymbolAddress((void**)&w1sh, g_w1s_h);
    cudaGetSymbolAddress((void**)&w1sl, g_w1s_l);
    cudaGetSymbolAddress((void**)&w1nh, g_w1n_h);
    cudaGetSymbolAddress((void**)&w1nl, g_w1n_l);
    cudaGetSymbolAddress((void**)&w2sh, g_w2s_h);
    cudaGetSymbolAddress((void**)&w2sl, g_w2s_l);
    cudaGetSymbolAddress((void**)&w2nh, g_w2n_h);
    cudaGetSymbolAddress((void**)&w2nl, g_w2n_l);

    const int SMEM_DUAL = 4 * A_TILE_B + 4 * B_TILE_B;  // 59392
    const int SMEM_PAIR = 2 * A_TILE_B + 4 * B_TILE_B;  // 38912
    cudaFuncSetAttribute(k_mm_dual, cudaFuncAttributeMaxDynamicSharedMemorySize, SMEM_DUAL);
    cudaFuncSetAttribute(k_mm_pair, cudaFuncAttributeMaxDynamicSharedMemorySize, SMEM_PAIR);

    // CSR build
    k_zero_cnt<<<(N_NODES + 255) / 256, 256>>>();
    k_hist<<<(E + 255) / 256, 256>>>(mdst, E);
    k_scan<<<1, 1024>>>();
    k_fill<<<(E + 255) / 256, 256>>>(msrc, mdst, E);

    // weight split (single launch, 4 matrices)
    k_wprep_all<<<(4 * 32768 + 255) / 256, 256>>>(W1s, W1n, W2s, W2n);

    // layer 1
    k_agg128<<<(N_NODES + 7) / 8, 256>>>(x, p_neigh1);
    {
        dim3 grid(D_HID / 64, (N_NODES + 127) / 128);
        k_mm_dual<<<grid, 256, SMEM_DUAL>>>(x, p_neigh1, w1sh, w1sl, w1nh, w1nl,
                                            b1, p_h1, N_NODES, D_HID, D_IN);
    }
    // layer 2: project then aggregate
    {
        dim3 grid(D_OUT / 64, (N_NODES + 127) / 128);
        k_mm_pair<<<grid, 256, SMEM_PAIR>>>(p_h1, w2sh, w2sl, w2nh, w2nl,
                                            b2, p_s2, p_t2, N_NODES, D_OUT, D_HID);
    }
    k_agg2_scores<<<(N_NODES + 7) / 8, 256>>>(Wp);

    // edge scoring
    k_edge_scores<<<(EP + EN + 255) / 256, 256>>>(psrc, pdst, nsrc, ndst, bp, out, EP, EN);
}

// round 8
// speedup vs baseline: 1.0582x; 1.0170x over previous
#include <cuda_runtime.h>
#include <cuda_bf16.h>
#include <cstdint>

#define N_NODES 50000
#define MAX_E   800000
#define D_IN    128
#define D_HID   256
#define D_OUT   128

// ---------------- scratch (static device globals; no allocation) ----------------
__device__ float g_neigh1[(size_t)N_NODES * D_IN];
__device__ float g_h1[(size_t)N_NODES * D_HID];
__device__ float g_s2[(size_t)N_NODES * D_OUT];
__device__ float g_t2[(size_t)N_NODES * D_OUT];
__device__ float g_sA[N_NODES];
__device__ float g_sB[N_NODES];
__device__ int   g_cnt[N_NODES];
__device__ int   g_rowptr[N_NODES + 1];
__device__ int   g_cursor[N_NODES];
__device__ int   g_csr_src[MAX_E];

// pre-split bf16 weights, same (K,N) layout as the fp32 originals
__device__ __nv_bfloat16 g_w1s_h[D_IN * D_HID], g_w1s_l[D_IN * D_HID];
__device__ __nv_bfloat16 g_w1n_h[D_IN * D_HID], g_w1n_l[D_IN * D_HID];
__device__ __nv_bfloat16 g_w2s_h[D_HID * D_OUT], g_w2s_l[D_HID * D_OUT];
__device__ __nv_bfloat16 g_w2n_h[D_HID * D_OUT], g_w2n_l[D_HID * D_OUT];

// ---------------- helpers ----------------
__device__ __forceinline__ uint32_t smem_u32(const void* p) {
    uint32_t a;
    asm("{ .reg .u64 t; cvta.to.shared.u64 t, %1; cvt.u32.u64 %0, t; }" : "=r"(a) : "l"(p));
    return a;
}
__device__ __forceinline__ uint32_t bpack(__nv_bfloat16 a, __nv_bfloat16 b) {
    return (uint32_t)__bfloat16_as_ushort(a) | ((uint32_t)__bfloat16_as_ushort(b) << 16);
}
__device__ __forceinline__ void split4(float4 v, uint32_t* h, uint32_t* l) {
    __nv_bfloat16 hx = __float2bfloat16_rn(v.x);
    __nv_bfloat16 hy = __float2bfloat16_rn(v.y);
    __nv_bfloat16 hz = __float2bfloat16_rn(v.z);
    __nv_bfloat16 hw = __float2bfloat16_rn(v.w);
    h[0] = bpack(hx, hy);
    h[1] = bpack(hz, hw);
    __nv_bfloat16 lx = __float2bfloat16_rn(v.x - __bfloat162float(hx));
    __nv_bfloat16 ly = __float2bfloat16_rn(v.y - __bfloat162float(hy));
    __nv_bfloat16 lz = __float2bfloat16_rn(v.z - __bfloat162float(hz));
    __nv_bfloat16 lw = __float2bfloat16_rn(v.w - __bfloat162float(hw));
    l[0] = bpack(lx, ly);
    l[1] = bpack(lz, lw);
}

#define LDSM_X4(r0, r1, r2, r3, addr) \
    asm volatile("ldmatrix.sync.aligned.m8n8.x4.shared.b16 {%0,%1,%2,%3}, [%4];" \
                 : "=r"(r0), "=r"(r1), "=r"(r2), "=r"(r3) : "r"(addr))
#define LDSM_X4T(r0, r1, r2, r3, addr) \
    asm volatile("ldmatrix.sync.aligned.m8n8.x4.trans.shared.b16 {%0,%1,%2,%3}, [%4];" \
                 : "=r"(r0), "=r"(r1), "=r"(r2), "=r"(r3) : "r"(addr))
#define MMA_BF16(c, a, b) \
    asm volatile("mma.sync.aligned.m16n8k16.row.col.f32.bf16.bf16.f32 " \
                 "{%0,%1,%2,%3}, {%4,%5,%6,%7}, {%8,%9}, {%0,%1,%2,%3};" \
                 : "+f"((c)[0]), "+f"((c)[1]), "+f"((c)[2]), "+f"((c)[3]) \
                 : "r"((a)[0]), "r"((a)[1]), "r"((a)[2]), "r"((a)[3]), \
                   "r"((b)[0]), "r"((b)[1]))
#define CP_ASYNC16(saddr, gptr) \
    asm volatile("cp.async.cg.shared.global [%0], [%1], 16;" :: "r"(saddr), "l"(gptr))
#define CP_COMMIT() asm volatile("cp.async.commit_group;")
#define CP_WAIT(n)  asm volatile("cp.async.wait_group %0;" :: "n"(n))

// ---------------- CSR build ----------------
__global__ void k_hist(const int* __restrict__ dst, int E) {
    int e = blockIdx.x * blockDim.x + threadIdx.x;
    if (e < E) atomicAdd(&g_cnt[dst[e]], 1);
}
__global__ void k_scan() {
    const int T = 1024;
    const int C = (N_NODES + T - 1) / T;
    __shared__ int partial[T];
    int t = threadIdx.x;
    int base = t * C;
    int s = 0;
    for (int i = 0; i < C; i++) {
        int idx = base + i;
        if (idx < N_NODES) s += g_cnt[idx];
    }
    partial[t] = s;
    __syncthreads();
    for (int off = 1; off < T; off <<= 1) {
        int v = (t >= off) ? partial[t - off] : 0;
        __syncthreads();
        partial[t] += v;
        __syncthreads();
    }
    int run = partial[t] - s;
    for (int i = 0; i < C; i++) {
        int idx = base + i;
        if (idx < N_NODES) {
            g_rowptr[idx] = run;
            g_cursor[idx] = run;
            run += g_cnt[idx];
        }
    }
    if (t == 0) g_rowptr[N_NODES] = partial[T - 1];
}
__global__ void k_fill(const int* __restrict__ src, const int* __restrict__ dst, int E) {
    int e = blockIdx.x * blockDim.x + threadIdx.x;
    if (e < E) {
        int d = dst[e];
        int pos = atomicAdd(&g_cursor[d], 1);
        g_csr_src[pos] = src[e];
    }
}

// ---------------- layer-1 aggregation (unrolled x2, round-5 proven) ----------------
__global__ void k_agg128(const float* __restrict__ feat, float* __restrict__ out) {
    int warps_per_blk = blockDim.x >> 5;
    int n = blockIdx.x * warps_per_blk + (threadIdx.x >> 5);
    if (n >= N_NODES) return;
    int lane = threadIdx.x & 31;
    int beg = g_rowptr[n], end = g_rowptr[n + 1];

    float4 acc0 = {0.f, 0.f, 0.f, 0.f};
    float4 acc1 = {0.f, 0.f, 0.f, 0.f};
    int j = beg;
    for (; j + 1 < end; j += 2) {
        int s0 = g_csr_src[j];
        int s1 = g_csr_src[j + 1];
        float4 v0 = __ldg(&((const float4*)(feat + (size_t)s0 * 128))[lane]);
        float4 v1 = __ldg(&((const float4*)(feat + (size_t)s1 * 128))[lane]);
        acc0.x += v0.x; acc0.y += v0.y; acc0.z += v0.z; acc0.w += v0.w;
        acc1.x += v1.x; acc1.y += v1.y; acc1.z += v1.z; acc1.w += v1.w;
    }
    if (j < end) {
        int s0 = g_csr_src[j];
        float4 v0 = __ldg(&((const float4*)(feat + (size_t)s0 * 128))[lane]);
        acc0.x += v0.x; acc0.y += v0.y; acc0.z += v0.z; acc0.w += v0.w;
    }
    acc0.x += acc1.x; acc0.y += acc1.y; acc0.z += acc1.z; acc0.w += acc1.w;
    int deg = end - beg;
    float inv = (deg > 0) ? 1.f / (float)deg : 0.f;
    float4 o = {acc0.x * inv, acc0.y * inv, acc0.z * inv, acc0.w * inv};
    ((float4*)(out + (size_t)n * 128))[lane] = o;
}

// ---------------- weight split + cnt zeroing, one launch ----------------
__global__ void k_wprep_all(
    const float* __restrict__ W1s, const float* __restrict__ W1n,
    const float* __restrict__ W2s, const float* __restrict__ W2n)
{
    int i = blockIdx.x * blockDim.x + threadIdx.x;
    if (i < N_NODES) g_cnt[i] = 0;
    if (i >= 4 * 32768) return;
    int a = i >> 15, r = i & 32767;
    const float* W = (a == 0) ? W1s : (a == 1) ? W1n : (a == 2) ? W2s : W2n;
    __nv_bfloat16* hi = (a == 0) ? g_w1s_h : (a == 1) ? g_w1n_h : (a == 2) ? g_w2s_h : g_w2n_h;
    __nv_bfloat16* lo = (a == 0) ? g_w1s_l : (a == 1) ? g_w1n_l : (a == 2) ? g_w2s_l : g_w2n_l;
    float w = W[r];
    __nv_bfloat16 h = __float2bfloat16_rn(w);
    hi[r] = h;
    lo[r] = __float2bfloat16_rn(w - __bfloat162float(h));
}

// ================= bf16x3 mma.sync GEMMs: swizzled-B double-buffer =================
// CTA tile 128(M) x 64(N), BK=32. 8 warps: wm=wid&3 (M), wn=wid>>2 (N).
// A tiles: 128 rows x 40 bf16 (80B row = 16x5), single-buffered.
// B tiles: 32 rows x 64 bf16, 128B rows with XOR-swizzle (unit ^= row&7),
//          double-buffered via cp.async. B_TILE_B = 4096.
#define A_TILE_B 10240
#define B_TILE_B 4096

// -------- layer 1: C = relu(A1@B1 + A2@B2 + bias) --------
__global__ void __launch_bounds__(256) k_mm_dual(
    const float* __restrict__ A1, const float* __restrict__ A2,
    const __nv_bfloat16* __restrict__ B1h, const __nv_bfloat16* __restrict__ B1l,
    const __nv_bfloat16* __restrict__ B2h, const __nv_bfloat16* __restrict__ B2l,
    const float* __restrict__ bias, float* __restrict__ C,
    int M, int N, int K)
{
    extern __shared__ char smem[];
    const int OA1H = 0, OA1L = A_TILE_B, OA2H = 2 * A_TILE_B, OA2L = 3 * A_TILE_B;
    const int OB_BASE = 4 * A_TILE_B;          // 2 buffers x 4 tiles x 4096
    uint32_t sb = smem_u32(smem);

    int tid = threadIdx.x, lane = tid & 31, wid = tid >> 5;
    int wm = wid & 3, wn = wid >> 2;
    int bm = blockIdx.y * 128, bn = blockIdx.x * 64;
    const int nch = K >> 5;

    // B cp.async slot (swizzled)
    int brow = tid >> 3, bseg = tid & 7;
    uint32_t bso = (uint32_t)(brow * 128 + ((bseg ^ (brow & 7)) << 4));
    const __nv_bfloat16* gB[4] = {B1h, B1l, B2h, B2l};

    float acc[2][4][4];
#pragma unroll
    for (int i = 0; i < 2; i++)
#pragma unroll
        for (int j = 0; j < 4; j++)
#pragma unroll
            for (int q = 0; q < 4; q++) acc[i][j][q] = 0.f;

    // prologue: B chunk0 -> buf0
    {
        size_t ge = (size_t)brow * N + bn + bseg * 8;
#pragma unroll
        for (int t = 0; t < 4; t++)
            CP_ASYNC16(sb + OB_BASE + t * B_TILE_B + bso, gB[t] + ge);
        CP_COMMIT();
    }

    for (int chunk = 0; chunk < nch; chunk++) {
        int k0 = chunk << 5;
        int obuf = OB_BASE + (chunk & 1) * 4 * B_TILE_B;

        // stage A (split on the fly, round-5 style)
#pragma unroll
        for (int q = 0; q < 4; q++) {
            int slot = tid + q * 256;
            int row = slot >> 3, k4 = (slot & 7) * 4;
            int gr = bm + row;
            float4 v1 = {0.f, 0.f, 0.f, 0.f}, v2 = {0.f, 0.f, 0.f, 0.f};
            if (gr < M) {
                v1 = *(const float4*)(A1 + (size_t)gr * K + k0 + k4);
                v2 = *(const float4*)(A2 + (size_t)gr * K + k0 + k4);
            }
            uint32_t h[2], l[2];
            int si = row * 20 + (k4 >> 1);
            split4(v1, h, l);
            ((uint32_t*)(smem + OA1H))[si] = h[0];
            ((uint32_t*)(smem + OA1H))[si + 1] = h[1];
            ((uint32_t*)(smem + OA1L))[si] = l[0];
            ((uint32_t*)(smem + OA1L))[si + 1] = l[1];
            split4(v2, h, l);
            ((uint32_t*)(smem + OA2H))[si] = h[0];
            ((uint32_t*)(smem + OA2H))[si + 1] = h[1];
            ((uint32_t*)(smem + OA2L))[si] = l[0];
            ((uint32_t*)(smem + OA2L))[si + 1] = l[1];
        }

        // prefetch next B chunk into other buffer
        if (chunk + 1 < nch) {
            int nbuf = OB_BASE + ((chunk + 1) & 1) * 4 * B_TILE_B;
            size_t ge = (size_t)(((chunk + 1) << 5) + brow) * N + bn + bseg * 8;
#pragma unroll
            for (int t = 0; t < 4; t++)
                CP_ASYNC16(sb + nbuf + t * B_TILE_B + bso, gB[t] + ge);
            CP_COMMIT();
            CP_WAIT(1);
        } else {
            CP_WAIT(0);
        }
        __syncthreads();

#pragma unroll
        for (int kk = 0; kk < 2; kk++) {
            uint32_t fa1h[2][4], fa1l[2][4], fa2h[2][4], fa2l[2][4];
#pragma unroll
            for (int mi = 0; mi < 2; mi++) {
                uint32_t aoff = (uint32_t)((wm * 32 + mi * 16 + (lane & 15)) * 80 +
                                           (lane >> 4) * 16 + kk * 32);
                LDSM_X4(fa1h[mi][0], fa1h[mi][1], fa1h[mi][2], fa1h[mi][3], sb + OA1H + aoff);
                LDSM_X4(fa1l[mi][0], fa1l[mi][1], fa1l[mi][2], fa1l[mi][3], sb + OA1L + aoff);
                LDSM_X4(fa2h[mi][0], fa2h[mi][1], fa2h[mi][2], fa2h[mi][3], sb + OA2H + aoff);
                LDSM_X4(fa2l[mi][0], fa2l[mi][1], fa2l[mi][2], fa2l[mi][3], sb + OA2L + aoff);
            }
            uint32_t fb1h[4][2], fb1l[4][2], fb2h[4][2], fb2l[4][2];
#pragma unroll
            for (int np = 0; np < 2; np++) {
                int r = kk * 16 + (lane & 7) + ((lane >> 3) & 1) * 8;
                int cu = wn * 4 + np * 2 + (lane >> 4);
                uint32_t boff = (uint32_t)(r * 128 + ((cu ^ (r & 7)) << 4));
                LDSM_X4T(fb1h[2 * np][0], fb1h[2 * np][1], fb1h[2 * np + 1][0], fb1h[2 * np + 1][1], sb + obuf + 0 * B_TILE_B + boff);
                LDSM_X4T(fb1l[2 * np][0], fb1l[2 * np][1], fb1l[2 * np + 1][0], fb1l[2 * np + 1][1], sb + obuf + 1 * B_TILE_B + boff);
                LDSM_X4T(fb2h[2 * np][0], fb2h[2 * np][1], fb2h[2 * np + 1][0], fb2h[2 * np + 1][1], sb + obuf + 2 * B_TILE_B + boff);
                LDSM_X4T(fb2l[2 * np][0], fb2l[2 * np][1], fb2l[2 * np + 1][0], fb2l[2 * np + 1][1], sb + obuf + 3 * B_TILE_B + boff);
            }
#pragma unroll
            for (int mi = 0; mi < 2; mi++)
#pragma unroll
                for (int nj = 0; nj < 4; nj++) {
                    MMA_BF16(acc[mi][nj], fa1h[mi], fb1h[nj]);
                    MMA_BF16(acc[mi][nj], fa1h[mi], fb1l[nj]);
                    MMA_BF16(acc[mi][nj], fa1l[mi], fb1h[nj]);
                    MMA_BF16(acc[mi][nj], fa2h[mi], fb2h[nj]);
                    MMA_BF16(acc[mi][nj], fa2h[mi], fb2l[nj]);
                    MMA_BF16(acc[mi][nj], fa2l[mi], fb2h[nj]);
                }
        }
        __syncthreads();
    }

    // epilogue
    int g = lane >> 2, c2 = (lane & 3) * 2;
#pragma unroll
    for (int mi = 0; mi < 2; mi++)
#pragma unroll
        for (int nj = 0; nj < 4; nj++) {
            int col = bn + wn * 32 + nj * 8 + c2;
            float2 bv = *(const float2*)(bias + col);
            int r0 = bm + wm * 32 + mi * 16 + g;
            if (r0 < M) {
                float2 o;
                o.x = fmaxf(acc[mi][nj][0] + bv.x, 0.f);
                o.y = fmaxf(acc[mi][nj][1] + bv.y, 0.f);
                *(float2*)(C + (size_t)r0 * N + col) = o;
            }
            int r1 = r0 + 8;
            if (r1 < M) {
                float2 o;
                o.x = fmaxf(acc[mi][nj][2] + bv.x, 0.f);
                o.y = fmaxf(acc[mi][nj][3] + bv.y, 0.f);
                *(float2*)(C + (size_t)r1 * N + col) = o;
            }
        }
}

// -------- layer 2: S = A@Bs + bias, T = A@Bt --------
__global__ void __launch_bounds__(256) k_mm_pair(
    const float* __restrict__ A,
    const __nv_bfloat16* __restrict__ Bsh, const __nv_bfloat16* __restrict__ Bsl,
    const __nv_bfloat16* __restrict__ Bth, const __nv_bfloat16* __restrict__ Btl,
    const float* __restrict__ bias, float* __restrict__ S, float* __restrict__ T,
    int M, int N, int K)
{
    extern __shared__ char smem[];
    const int OAH = 0, OAL = A_TILE_B;
    const int OB_BASE = 2 * A_TILE_B;
    uint32_t sb = smem_u32(smem);

    int tid = threadIdx.x, lane = tid & 31, wid = tid >> 5;
    int wm = wid & 3, wn = wid >> 2;
    int bm = blockIdx.y * 128, bn = blockIdx.x * 64;
    const int nch = K >> 5;

    int brow = tid >> 3, bseg = tid & 7;
    uint32_t bso = (uint32_t)(brow * 128 + ((bseg ^ (brow & 7)) << 4));
    const __nv_bfloat16* gB[4] = {Bsh, Bsl, Bth, Btl};

    float accS[2][4][4], accT[2][4][4];
#pragma unroll
    for (int i = 0; i < 2; i++)
#pragma unroll
        for (int j = 0; j < 4; j++)
#pragma unroll
            for (int q = 0; q < 4; q++) { accS[i][j][q] = 0.f; accT[i][j][q] = 0.f; }

    {
        size_t ge = (size_t)brow * N + bn + bseg * 8;
#pragma unroll
        for (int t = 0; t < 4; t++)
            CP_ASYNC16(sb + OB_BASE + t * B_TILE_B + bso, gB[t] + ge);
        CP_COMMIT();
    }

    for (int chunk = 0; chunk < nch; chunk++) {
        int k0 = chunk << 5;
        int obuf = OB_BASE + (chunk & 1) * 4 * B_TILE_B;

#pragma unroll
        for (int q = 0; q < 4; q++) {
            int slot = tid + q * 256;
            int row = slot >> 3, k4 = (slot & 7) * 4;
            int gr = bm + row;
            float4 v = {0.f, 0.f, 0.f, 0.f};
            if (gr < M) v = *(const float4*)(A + (size_t)gr * K + k0 + k4);
            uint32_t h[2], l[2];
            split4(v, h, l);
            int si = row * 20 + (k4 >> 1);
            ((uint32_t*)(smem + OAH))[si] = h[0];
            ((uint32_t*)(smem + OAH))[si + 1] = h[1];
            ((uint32_t*)(smem + OAL))[si] = l[0];
            ((uint32_t*)(smem + OAL))[si + 1] = l[1];
        }

        if (chunk + 1 < nch) {
            int nbuf = OB_BASE + ((chunk + 1) & 1) * 4 * B_TILE_B;
            size_t ge = (size_t)(((chunk + 1) << 5) + brow) * N + bn + bseg * 8;
#pragma unroll
            for (int t = 0; t < 4; t++)
                CP_ASYNC16(sb + nbuf + t * B_TILE_B + bso, gB[t] + ge);
            CP_COMMIT();
            CP_WAIT(1);
        } else {
            CP_WAIT(0);
        }
        __syncthreads();

#pragma unroll
        for (int kk = 0; kk < 2; kk++) {
            uint32_t fah[2][4], fal[2][4];
#pragma unroll
            for (int mi = 0; mi < 2; mi++) {
                uint32_t aoff = (uint32_t)((wm * 32 + mi * 16 + (lane & 15)) * 80 +
                                           (lane >> 4) * 16 + kk * 32);
                LDSM_X4(fah[mi][0], fah[mi][1], fah[mi][2], fah[mi][3], sb + OAH + aoff);
                LDSM_X4(fal[mi][0], fal[mi][1], fal[mi][2], fal[mi][3], sb + OAL + aoff);
            }
            uint32_t fbsh[4][2], fbsl[4][2], fbth[4][2], fbtl[4][2];
#pragma unroll
            for (int np = 0; np < 2; np++) {
                int r = kk * 16 + (lane & 7) + ((lane >> 3) & 1) * 8;
                int cu = wn * 4 + np * 2 + (lane >> 4);
                uint32_t boff = (uint32_t)(r * 128 + ((cu ^ (r & 7)) << 4));
                LDSM_X4T(fbsh[2 * np][0], fbsh[2 * np][1], fbsh[2 * np + 1][0], fbsh[2 * np + 1][1], sb + obuf + 0 * B_TILE_B + boff);
                LDSM_X4T(fbsl[2 * np][0], fbsl[2 * np][1], fbsl[2 * np + 1][0], fbsl[2 * np + 1][1], sb + obuf + 1 * B_TILE_B + boff);
                LDSM_X4T(fbth[2 * np][0], fbth[2 * np][1], fbth[2 * np + 1][0], fbth[2 * np + 1][1], sb + obuf + 2 * B_TILE_B + boff);
                LDSM_X4T(fbtl[2 * np][0], fbtl[2 * np][1], fbtl[2 * np + 1][0], fbtl[2 * np + 1][1], sb + obuf + 3 * B_TILE_B + boff);
            }
#pragma unroll
            for (int mi = 0; mi < 2; mi++)
#pragma unroll
                for (int nj = 0; nj < 4; nj++) {
                    MMA_BF16(accS[mi][nj], fah[mi], fbsh[nj]);
                    MMA_BF16(accS[mi][nj], fah[mi], fbsl[nj]);
                    MMA_BF16(accS[mi][nj], fal[mi], fbsh[nj]);
                    MMA_BF16(accT[mi][nj], fah[mi], fbth[nj]);
                    MMA_BF16(accT[mi][nj], fah[mi], fbtl[nj]);
                    MMA_BF16(accT[mi][nj], fal[mi], fbth[nj]);
                }
        }
        __syncthreads();
    }

    int g = lane >> 2, c2 = (lane & 3) * 2;
#pragma unroll
    for (int mi = 0; mi < 2; mi++)
#pragma unroll
        for (int nj = 0; nj < 4; nj++) {
            int col = bn + wn * 32 + nj * 8 + c2;
            float2 bv = *(const float2*)(bias + col);
            int r0 = bm + wm * 32 + mi * 16 + g;
            if (r0 < M) {
                float2 os = {accS[mi][nj][0] + bv.x, accS[mi][nj][1] + bv.y};
                *(float2*)(S + (size_t)r0 * N + col) = os;
                float2 ot = {accT[mi][nj][0], accT[mi][nj][1]};
                *(float2*)(T + (size_t)r0 * N + col) = ot;
            }
            int r1 = r0 + 8;
            if (r1 < M) {
                float2 os = {accS[mi][nj][2] + bv.x, accS[mi][nj][3] + bv.y};
                *(float2*)(S + (size_t)r1 * N + col) = os;
                float2 ot = {accT[mi][nj][2], accT[mi][nj][3]};
                *(float2*)(T + (size_t)r1 * N + col) = ot;
            }
        }
}

// ---------------- fused layer-2 aggregation + node scores (unrolled x2) ----------------
__global__ void k_agg2_scores(const float* __restrict__ Wp) {
    int warps_per_blk = blockDim.x >> 5;
    int n = blockIdx.x * warps_per_blk + (threadIdx.x >> 5);
    if (n >= N_NODES) return;
    int lane = threadIdx.x & 31;
    int beg = g_rowptr[n], end = g_rowptr[n + 1];

    float4 acc0 = {0.f, 0.f, 0.f, 0.f};
    float4 acc1 = {0.f, 0.f, 0.f, 0.f};
    int j = beg;
    for (; j + 1 < end; j += 2) {
        int s0 = g_csr_src[j];
        int s1 = g_csr_src[j + 1];
        float4 v0 = __ldg(&((const float4*)(g_t2 + (size_t)s0 * 128))[lane]);
        float4 v1 = __ldg(&((const float4*)(g_t2 + (size_t)s1 * 128))[lane]);
        acc0.x += v0.x; acc0.y += v0.y; acc0.z += v0.z; acc0.w += v0.w;
        acc1.x += v1.x; acc1.y += v1.y; acc1.z += v1.z; acc1.w += v1.w;
    }
    if (j < end) {
        int s0 = g_csr_src[j];
        float4 v0 = __ldg(&((const float4*)(g_t2 + (size_t)s0 * 128))[lane]);
        acc0.x += v0.x; acc0.y += v0.y; acc0.z += v0.z; acc0.w += v0.w;
    }
    acc0.x += acc1.x; acc0.y += acc1.y; acc0.z += acc1.z; acc0.w += acc1.w;
    int deg = end - beg;
    float inv = (deg > 0) ? 1.f / (float)deg : 0.f;
    float4 sv = ((const float4*)(g_s2 + (size_t)n * 128))[lane];
    float4 h;
    h.x = sv.x + acc0.x * inv;
    h.y = sv.y + acc0.y * inv;
    h.z = sv.z + acc0.z * inv;
    h.w = sv.w + acc0.w * inv;

    float4 wa = __ldg(&((const float4*)Wp)[lane]);
    float4 wb = __ldg(&((const float4*)Wp)[lane + 32]);
    float a = h.x * wa.x + h.y * wa.y + h.z * wa.z + h.w * wa.w;
    float b = h.x * wb.x + h.y * wb.y + h.z * wb.z + h.w * wb.w;
#pragma unroll
    for (int off = 16; off; off >>= 1) {
        a += __shfl_down_sync(0xFFFFFFFFu, a, off);
        b += __shfl_down_sync(0xFFFFFFFFu, b, off);
    }
    if (lane == 0) { g_sA[n] = a; g_sB[n] = b; }
}

__global__ void k_edge_scores(const int* __restrict__ psrc, const int* __restrict__ pdst,
                              const int* __restrict__ nsrc, const int* __restrict__ ndst,
                              const float* __restrict__ bp, float* __restrict__ out,
                              int EP, int EN) {
    int i = blockIdx.x * blockDim.x + threadIdx.x;
    float b = bp[0];
    if (i < EP) {
        out[i] = g_sA[psrc[i]] + g_sB[pdst[i]] + b;
    } else if (i < EP + EN) {
        int j = i - EP;
        out[i] = g_sA[nsrc[j]] + g_sB[ndst[j]] + b;
    }
}

// ---------------- launch ----------------
extern "C" void kernel_launch(void* const* d_in, const int* in_sizes, int n_in,
                              void* d_out, int out_size) {
    const float* x    = (const float*)d_in[0];
    const int* msrc   = (const int*)d_in[1];
    const int* mdst   = (const int*)d_in[2];
    const int* psrc   = (const int*)d_in[3];
    const int* pdst   = (const int*)d_in[4];
    const int* nsrc   = (const int*)d_in[5];
    const int* ndst   = (const int*)d_in[6];
    const float* W1s  = (const float*)d_in[7];
    const float* W1n  = (const float*)d_in[8];
    const float* b1   = (const float*)d_in[9];
    const float* W2s  = (const float*)d_in[10];
    const float* W2n  = (const float*)d_in[11];
    const float* b2   = (const float*)d_in[12];
    const float* Wp   = (const float*)d_in[13];
    const float* bp   = (const float*)d_in[14];
    float* out = (float*)d_out;

    int E  = in_sizes[1];
    int EP = in_sizes[3];
    int EN = in_sizes[5];

    float *p_neigh1, *p_h1, *p_s2, *p_t2;
    cudaGetSymbolAddress((void**)&p_neigh1, g_neigh1);
    cudaGetSymbolAddress((void**)&p_h1,     g_h1);
    cudaGetSymbolAddress((void**)&p_s2,     g_s2);
    cudaGetSymbolAddress((void**)&p_t2,     g_t2);

    __nv_bfloat16 *w1sh, *w1sl, *w1nh, *w1nl, *w2sh, *w2sl, *w2nh, *w2nl;
    cudaGetSymbolAddress((void**)&w1sh, g_w1s_h);
    cudaGetSymbolAddress((void**)&w1sl, g_w1s_l);
    cudaGetSymbolAddress((void**)&w1nh, g_w1n_h);
    cudaGetSymbolAddress((void**)&w1nl, g_w1n_l);
    cudaGetSymbolAddress((void**)&w2sh, g_w2s_h);
    cudaGetSymbolAddress((void**)&w2sl, g_w2s_l);
    cudaGetSymbolAddress((void**)&w2nh, g_w2n_h);
    cudaGetSymbolAddress((void**)&w2nl, g_w2n_l);

    const int SMEM_DUAL = 4 * A_TILE_B + 2 * 4 * B_TILE_B;  // 73728 -> 3 CTAs/SM
    const int SMEM_PAIR = 2 * A_TILE_B + 2 * 4 * B_TILE_B;  // 53248 -> 4 CTAs/SM
    cudaFuncSetAttribute(k_mm_dual, cudaFuncAttributeMaxDynamicSharedMemorySize, SMEM_DUAL);
    cudaFuncSetAttribute(k_mm_pair, cudaFuncAttributeMaxDynamicSharedMemorySize, SMEM_PAIR);

    // weight split + cnt zeroing (one launch), then CSR build
    k_wprep_all<<<(4 * 32768 + 255) / 256, 256>>>(W1s, W1n, W2s, W2n);
    k_hist<<<(E + 255) / 256, 256>>>(mdst, E);
    k_scan<<<1, 1024>>>();
    k_fill<<<(E + 255) / 256, 256>>>(msrc, mdst, E);

    // layer 1
    k_agg128<<<(N_NODES + 7) / 8, 256>>>(x, p_neigh1);
    {
        dim3 grid(D_HID / 64, (N_NODES + 127) / 128);
        k_mm_dual<<<grid, 256, SMEM_DUAL>>>(x, p_neigh1, w1sh, w1sl, w1nh, w1nl,
                                            b1, p_h1, N_NODES, D_HID, D_IN);
    }
    // layer 2: project then aggregate
    {
        dim3 grid(D_OUT / 64, (N_NODES + 127) / 128);
        k_mm_pair<<<grid, 256, SMEM_PAIR>>>(p_h1, w2sh, w2sl, w2nh, w2nl,
                                            b2, p_s2, p_t2, N_NODES, D_OUT, D_HID);
    }
    k_agg2_scores<<<(N_NODES + 7) / 8, 256>>>(Wp);

    // edge scoring
    k_edge_scores<<<(EP + EN + 255) / 256, 256>>>(psrc, pdst, nsrc, ndst, bp, out, EP, EN);
}